// round 1
// baseline (speedup 1.0000x reference)
#include <cuda_runtime.h>

#define BATCH  4
#define SEQQ   2048
#define SEQK   2048
#define DMODEL 512
#define NH     8
#define DHEAD  64
#define NBH    (BATCH*NH)

// ---------------- scratch (static device globals; no allocation) ----------------
__device__ float g_qp [ (size_t)NBH*SEQQ*DHEAD ];   // [B,H,S,DH] 16 MB
__device__ float g_kp [ (size_t)NBH*SEQK*DHEAD ];
__device__ float g_vp [ (size_t)NBH*SEQK*DHEAD ];
__device__ float g_ctx[ (size_t)BATCH*SEQQ*DMODEL ]; // [B,Q,D]

// =====================================================================
// SGEMM: C = A[M,512] @ W[N,512]^T   (both operands K-major, row-major)
// BM=BN=128, BK=8, 256 threads, 8x8 per-thread tile.
// PROJ=1: scatter output to [B,H,S,DH] layout. PROJ=0: plain [M,N].
// =====================================================================
template<int PROJ>
__global__ __launch_bounds__(256, 2)
void sgemm_xwt(const float* __restrict__ A, const float* __restrict__ W,
               float* __restrict__ C)
{
    __shared__ float As[8][128];
    __shared__ float Bs[8][128];

    const int tid = threadIdx.x;
    const int m0  = blockIdx.y * 128;
    const int n0  = blockIdx.x * 128;

    const int lr = tid >> 1;          // 0..127
    const int lc = (tid & 1) << 2;    // 0 or 4

    const int ty = tid >> 4;          // 0..15 (row group)
    const int tx = tid & 15;          // 0..15 (col group)

    float acc[8][8];
#pragma unroll
    for (int i = 0; i < 8; i++)
#pragma unroll
        for (int j = 0; j < 8; j++) acc[i][j] = 0.f;

    const float* Aptr = A + (size_t)(m0 + lr) * DMODEL + lc;
    const float* Wptr = W + (size_t)(n0 + lr) * DMODEL + lc;

    for (int k0 = 0; k0 < DMODEL; k0 += 8) {
        float4 a4 = *(const float4*)(Aptr + k0);
        float4 w4 = *(const float4*)(Wptr + k0);
        As[lc + 0][lr] = a4.x; As[lc + 1][lr] = a4.y;
        As[lc + 2][lr] = a4.z; As[lc + 3][lr] = a4.w;
        Bs[lc + 0][lr] = w4.x; Bs[lc + 1][lr] = w4.y;
        Bs[lc + 2][lr] = w4.z; Bs[lc + 3][lr] = w4.w;
        __syncthreads();

#pragma unroll
        for (int kk = 0; kk < 8; kk++) {
            float ra[8], rb[8];
#pragma unroll
            for (int i = 0; i < 8; i++) ra[i] = As[kk][ty * 8 + i];
#pragma unroll
            for (int j = 0; j < 8; j++) rb[j] = Bs[kk][tx * 8 + j];
#pragma unroll
            for (int i = 0; i < 8; i++)
#pragma unroll
                for (int j = 0; j < 8; j++)
                    acc[i][j] += ra[i] * rb[j];
        }
        __syncthreads();
    }

#pragma unroll
    for (int i = 0; i < 8; i++) {
        const int m = m0 + ty * 8 + i;
#pragma unroll
        for (int j = 0; j < 8; j++) {
            const int n = n0 + tx * 8 + j;
            if (PROJ) {
                // m = b*2048 + s ; n = h*64 + dh  ->  [b][h][s][dh]
                const int b = m >> 11, s = m & 2047;
                const int h = n >> 6,  dh = n & 63;
                C[((((size_t)b * NH + h) * SEQQ + s) << 6) + dh] = acc[i][j];
            } else {
                C[(size_t)m * DMODEL + n] = acc[i][j];
            }
        }
    }
}

// =====================================================================
// Flash attention (fp32, online softmax), per block: 64 queries x one (b,h).
// Key tiles of 32. Only iterates over valid keys (mask == skipped work;
// exp(-1e6 - m) == 0 exactly in fp32 so this matches the reference).
// 128 threads. smem ~42 KB (static, < 48 KB).
// =====================================================================
__global__ __launch_bounds__(128)
void flash_attn(const int* __restrict__ valid_lens, float* __restrict__ ctx)
{
    __shared__ float sQ[64][65];   // padded: conflict-free column reads
    __shared__ float sK[32][65];
    __shared__ float sV[32][68];   // +4 pad: rows stay 16B-aligned for float4
    __shared__ float sP[64][33];

    const int tid = threadIdx.x;
    const int bh  = blockIdx.y;          // 0..31
    const int b   = bh >> 3;
    const int h   = bh & 7;
    const int q0  = blockIdx.x << 6;
    const int valid = valid_lens[b];

    const float* Qb = g_qp + ((size_t)bh * SEQQ + q0) * DHEAD;
    const float* Kb = g_kp + (size_t)bh * SEQK * DHEAD;
    const float* Vb = g_vp + (size_t)bh * SEQK * DHEAD;

    // load Q tile (64x64)
    for (int i = tid; i < 64 * 16; i += 128) {
        const int r = i >> 4, c4 = (i & 15) << 2;
        float4 v = *(const float4*)(Qb + r * DHEAD + c4);
        sQ[r][c4] = v.x; sQ[r][c4+1] = v.y; sQ[r][c4+2] = v.z; sQ[r][c4+3] = v.w;
    }

    // per-thread row state (2 threads per query row, each owns 32 dh cols)
    const int r    = tid >> 1;        // 0..63
    const int half = tid & 1;
    const int co   = half << 5;       // 0 or 32

    float m_prev = -1e30f, l_run = 0.f;
    float acc[32];
#pragma unroll
    for (int j = 0; j < 32; j++) acc[j] = 0.f;

    // score-stage mapping: 16x8 thread grid, each does 4x4 of the 64x32 tile
    const int ty = tid >> 3;   // 0..15
    const int tx = tid & 7;    // 0..7

    const int nTiles = (valid + 31) >> 5;
    for (int t = 0; t < nTiles; t++) {
        const int k0 = t << 5;
        __syncthreads();   // protect sK/sV/sP from previous iteration's readers

        // load K,V tiles (32x64 each)
        for (int i = tid; i < 32 * 16; i += 128) {
            const int kr = i >> 4, c4 = (i & 15) << 2;
            float4 kv = *(const float4*)(Kb + (size_t)(k0 + kr) * DHEAD + c4);
            sK[kr][c4] = kv.x; sK[kr][c4+1] = kv.y; sK[kr][c4+2] = kv.z; sK[kr][c4+3] = kv.w;
            float4 vv = *(const float4*)(Vb + (size_t)(k0 + kr) * DHEAD + c4);
            sV[kr][c4] = vv.x; sV[kr][c4+1] = vv.y; sV[kr][c4+2] = vv.z; sV[kr][c4+3] = vv.w;
        }
        __syncthreads();

        // ---- S = Q K^T / 8, masked, into sP ----
        {
            float s[4][4];
#pragma unroll
            for (int i = 0; i < 4; i++)
#pragma unroll
                for (int j = 0; j < 4; j++) s[i][j] = 0.f;

#pragma unroll 8
            for (int d = 0; d < 64; d++) {
                float qv[4], kv[4];
#pragma unroll
                for (int i = 0; i < 4; i++) qv[i] = sQ[ty + (i << 4)][d];
#pragma unroll
                for (int j = 0; j < 4; j++) kv[j] = sK[(tx << 2) + j][d];
#pragma unroll
                for (int i = 0; i < 4; i++)
#pragma unroll
                    for (int j = 0; j < 4; j++)
                        s[i][j] += qv[i] * kv[j];
            }
            const int rem = valid - k0;   // >= 1 inside loop range
#pragma unroll
            for (int i = 0; i < 4; i++)
#pragma unroll
                for (int j = 0; j < 4; j++) {
                    const int c = (tx << 2) + j;
                    sP[ty + (i << 4)][c] = (c < rem) ? s[i][j] * 0.125f : -1e30f;
                }
        }
        __syncthreads();

        // ---- online softmax for row r (both halves compute identical stats) ----
        {
            float mt = -1e30f;
#pragma unroll 8
            for (int c = 0; c < 32; c++) mt = fmaxf(mt, sP[r][c]);
            const float m_new = fmaxf(m_prev, mt);
            const float scale = __expf(m_prev - m_new);
            float p[32], psum = 0.f;
#pragma unroll 8
            for (int c = 0; c < 32; c++) { p[c] = __expf(sP[r][c] - m_new); psum += p[c]; }
            l_run = l_run * scale + psum;
            m_prev = m_new;
#pragma unroll
            for (int j = 0; j < 32; j++) acc[j] *= scale;
            // each half writes back its 16 columns (no duplicate writes)
#pragma unroll
            for (int c = 0; c < 16; c++) sP[r][(half << 4) + c] = p[(half << 4) + c];
        }
        __syncthreads();

        // ---- O += P V  (thread owns row r, dh cols [co, co+32)) ----
#pragma unroll 4
        for (int k = 0; k < 32; k++) {
            const float p = sP[r][k];
            const float4* vr = (const float4*)&sV[k][co];
#pragma unroll
            for (int j4 = 0; j4 < 8; j4++) {
                float4 v = vr[j4];
                acc[j4 * 4 + 0] += p * v.x;
                acc[j4 * 4 + 1] += p * v.y;
                acc[j4 * 4 + 2] += p * v.z;
                acc[j4 * 4 + 3] += p * v.w;
            }
        }
    }

    // epilogue: normalize and scatter to ctx [b][q][h*64+dh]
    const float inv = 1.f / l_run;
    float* out = ctx + ((size_t)b * SEQQ + q0 + r) * DMODEL + h * DHEAD + co;
#pragma unroll
    for (int j = 0; j < 32; j++) out[j] = acc[j] * inv;
}

// =====================================================================
// launch
// =====================================================================
extern "C" void kernel_launch(void* const* d_in, const int* in_sizes, int n_in,
                              void* d_out, int out_size)
{
    const float* queries    = (const float*)d_in[0];
    const float* keys       = (const float*)d_in[1];
    const float* values     = (const float*)d_in[2];
    const int*   valid_lens = (const int*)  d_in[3];
    const float* W_q        = (const float*)d_in[4];
    const float* W_k        = (const float*)d_in[5];
    const float* W_v        = (const float*)d_in[6];
    const float* W_o        = (const float*)d_in[7];
    float*       out        = (float*)d_out;

    float *qp, *kp, *vp, *ctx;
    cudaGetSymbolAddress((void**)&qp,  g_qp);
    cudaGetSymbolAddress((void**)&kp,  g_kp);
    cudaGetSymbolAddress((void**)&vp,  g_vp);
    cudaGetSymbolAddress((void**)&ctx, g_ctx);

    dim3 gridG(DMODEL / 128, (BATCH * SEQQ) / 128);   // (4, 64)
    sgemm_xwt<1><<<gridG, 256>>>(queries, W_q, qp);
    sgemm_xwt<1><<<gridG, 256>>>(keys,    W_k, kp);
    sgemm_xwt<1><<<gridG, 256>>>(values,  W_v, vp);

    dim3 gridF(SEQQ / 64, NBH);                       // (32, 32)
    flash_attn<<<gridF, 128>>>(valid_lens, ctx);

    sgemm_xwt<0><<<gridG, 256>>>(ctx, W_o, out);
}